// round 15
// baseline (speedup 1.0000x reference)
#include <cuda_runtime.h>
#include <cstdint>

// Fixed problem shape
#define BATCH 8
#define CDIM  64
#define NPTS  4096
#define KNN   20
#define TM    128    // targets per block == threads per block
#define TC    32     // candidate tile size
#define CAP   10     // per-thread candidate buffer slots (trigger at cnt>2)
#define NSPLIT 3
// 128 tiles of 32 split 43 / 43 / 42.
#define PART_TILES(p) ((p) == 2 ? 42 : 43)
#define PART_JBEG(p)  ((p) * 43 * TC)

// Cross-kernel scratch (device globals; no allocations).
__device__ float g_csq[BATCH * NPTS];
__device__ unsigned long long g_part[NSPLIT][KNN][BATCH * NPTS];

// Packed helpers: fma.rn.f32x2 = two independent rn-rounded fp32 FMAs.
__device__ __forceinline__ void fma2(unsigned long long& acc,
                                     unsigned long long a2,
                                     unsigned long long b2) {
    asm("fma.rn.f32x2 %0, %1, %2, %0;" : "+l"(acc) : "l"(a2), "l"(b2));
}
__device__ __forceinline__ unsigned long long dup2(float a) {
    unsigned long long r;
    asm("mov.b64 %0, {%1, %1};" : "=l"(r) : "f"(a));
    return r;
}
__device__ __forceinline__ void unpack2(unsigned long long v, float& lo, float& hi) {
    asm("mov.b64 {%0, %1}, %2;" : "=f"(lo), "=f"(hi) : "l"(v));
}
__device__ __forceinline__ void cp_async16(const float* smem_dst, const float* gmem_src) {
    uint32_t s = (uint32_t)__cvta_generic_to_shared(smem_dst);
    asm volatile("cp.async.ca.shared.global [%0], [%1], 16;" :: "r"(s), "l"(gmem_src));
}
#define CP_COMMIT() asm volatile("cp.async.commit_group;" ::: "memory")
#define CP_WAIT0()  asm volatile("cp.async.wait_group 0;" ::: "memory")

// ---------------------------------------------------------------------------
// Prologue: g_csq[b][n] = sum_c x[b][c][n]^2, ascending-c sequential FMA —
// bit-identical to every passing round's csq.
// ---------------------------------------------------------------------------
__global__ void __launch_bounds__(256) sq_all(const float* __restrict__ x) {
    int idx = blockIdx.x * 256 + threadIdx.x;   // 0 .. B*N-1
    int b = idx >> 12;
    int n = idx & (NPTS - 1);
    const float* xb = x + b * CDIM * NPTS;
    float s = 0.f;
#pragma unroll
    for (int c = 0; c < CDIM; c++) {
        float v = xb[c * NPTS + n];             // coalesced
        s = fmaf(v, v, s);
    }
    g_csq[idx] = s;
}

// ---------------------------------------------------------------------------
// Kernel 1: hot-loop/top-K code identical to the passing R14 kernel. Changes
// are occupancy-structural ONLY:
//  - NSPLIT=3 at TM=128: grid 768 -> 5.19 CTAs/SM, single wave, no cliff.
//  - __launch_bounds__(128, 5): caps regs at 102 so 5 CTAs/SM holds.
//  - single-buffered tile (double-buffering measured neutral in R11) so
//    static smem = 38.4KB -> <=40KB after granularity rounding -> cap 5.
// Per-lane distance arithmetic bit-identical to all passing rounds:
//   sequential ascending-c FMA dot & csq; d2 = fma(dot, -2, sqt + csq).
// Top-K: threshold + deferred buffer merge on packed u64 keys
// (d2_bits<<32 | idx) == exact lax.top_k (dist asc, lower idx first).
// ---------------------------------------------------------------------------
__global__ void __launch_bounds__(TM, 5) knn_part(const float* __restrict__ x) {
    __shared__ __align__(16) float s_tile[(CDIM + 1) * TC];  // 8.3 KB (+csq row)
    __shared__ unsigned long long s_top[KNN][TM];            // 20 KB sorted topK
    __shared__ unsigned long long s_buf[CAP][TM];            // 10 KB buffers

    const int b    = blockIdx.y;
    const int part = blockIdx.z;
    const int tid  = threadIdx.x;
    const int tgt  = blockIdx.x * TM + tid;
    const float* xb = x + b * CDIM * NPTS;
    const float* cq = g_csq + b * NPTS;
    const int jbeg   = PART_JBEG(part);
    const int ntiles = PART_TILES(part);

    // Target features -> registers; target squared norm (ascending c).
    float tq[CDIM];
    float sqt = 0.f;
#pragma unroll
    for (int c = 0; c < CDIM; c++) {
        tq[c] = xb[c * NPTS + tgt];
        sqt = fmaf(tq[c], tq[c], sqt);
    }

#pragma unroll
    for (int k = 0; k < KNN; k++) s_top[k][tid] = ~0ull;
    unsigned long long thresh = ~0ull;
    int cnt = 0;

    for (int t = 0; t < ntiles; t++) {
        const int j0 = jbeg + t * TC;
        __syncthreads();                        // done reading before restage
        // Stage tile (64 channel rows + csq row) via cp.async, 16B chunks.
#pragma unroll
        for (int k = 0; k < 4; k++) {
            int cid = tid * 4 + k;              // 0..511 chunk id
            int c = cid >> 3, i = cid & 7;
            cp_async16(s_tile + c * TC + i * 4, xb + c * NPTS + j0 + i * 4);
        }
        if (tid < 8)
            cp_async16(s_tile + CDIM * TC + tid * 4, cq + j0 + tid * 4);
        CP_COMMIT();
        CP_WAIT0();
        __syncthreads();                        // tile visible to all warps

        const float* sf  = s_tile;
        const float* csq = s_tile + CDIM * TC;

        for (int jg = 0; jg < TC; jg += 8) {
            unsigned long long a01 = 0, a23 = 0, a45 = 0, a67 = 0;
#pragma unroll
            for (int c = 0; c < CDIM; c++) {
                const ulonglong2* rp =
                    reinterpret_cast<const ulonglong2*>(sf + c * TC + jg);
                ulonglong2 v0 = rp[0];          // cands jg..jg+3
                ulonglong2 v1 = rp[1];          // cands jg+4..jg+7
                unsigned long long a2 = dup2(tq[c]);
                fma2(a01, a2, v0.x);
                fma2(a23, a2, v0.y);
                fma2(a45, a2, v1.x);
                fma2(a67, a2, v1.y);
            }
            float dots[8];
            unpack2(a01, dots[0], dots[1]);
            unpack2(a23, dots[2], dots[3]);
            unpack2(a45, dots[4], dots[5]);
            unpack2(a67, dots[6], dots[7]);

            float4 cs0 = *reinterpret_cast<const float4*>(csq + jg);
            float4 cs1 = *reinterpret_cast<const float4*>(csq + jg + 4);
            float csv[8] = {cs0.x, cs0.y, cs0.z, cs0.w,
                            cs1.x, cs1.y, cs1.z, cs1.w};
#pragma unroll
            for (int u = 0; u < 8; u++) {
                int   j = j0 + jg + u;
                float ts = sqt + csv[u];
                float d  = fmaf(dots[u], -2.0f, ts);  // one final rounding
                unsigned long long key =
                    ((unsigned long long)__float_as_uint(d) << 32) |
                    (unsigned int)j;
                // Branchless append (R14-proven): unconditional store,
                // predicated count. Junk beyond cnt is never read.
                s_buf[cnt][tid] = key;
                cnt += (int)((j != tgt) & (key < thresh));
            }
            // Deferred warp-wide merge; cnt<=2 carries + <=8 appends <= CAP.
            if (__any_sync(0xffffffffu, cnt > 2)) {
                for (int i = 0; i < cnt; i++) {
                    unsigned long long kv = s_buf[i][tid];
                    if (kv < s_top[KNN - 1][tid]) {
                        int k = KNN - 1;
                        while (k > 0 && s_top[k - 1][tid] > kv) {
                            s_top[k][tid] = s_top[k - 1][tid];
                            k--;
                        }
                        s_top[k][tid] = kv;
                    }
                }
                cnt = 0;
                thresh = s_top[KNN - 1][tid];
            }
        }
    }

    for (int i = 0; i < cnt; i++) {             // leftovers
        unsigned long long kv = s_buf[i][tid];
        if (kv < s_top[KNN - 1][tid]) {
            int k = KNN - 1;
            while (k > 0 && s_top[k - 1][tid] > kv) {
                s_top[k][tid] = s_top[k - 1][tid];
                k--;
            }
            s_top[k][tid] = kv;
        }
    }

    // Write sorted partial top-20 (coalesced in target index).
    const int col = b * NPTS + tgt;
#pragma unroll
    for (int p = 0; p < KNN; p++)
        g_part[part][p][col] = s_top[p][tid];
}

// ---------------------------------------------------------------------------
// Kernel 2: exact 3-way tournament merge of three sorted top-20 key lists.
// Keys are globally unique (index embedded) -> u64 order is total & exact.
// ---------------------------------------------------------------------------
__global__ void __launch_bounds__(256) knn_merge(float* __restrict__ out) {
    const int idx = blockIdx.x * 256 + threadIdx.x;     // 0 .. B*N-1
    const int b = idx >> 12;                            // NPTS = 4096
    const int n = idx & (NPTS - 1);
    const int base0 = ((0 * BATCH + b) * NPTS + n) * KNN;
    const int base1 = ((1 * BATCH + b) * NPTS + n) * KNN;
    const float ftgt = (float)n;

    int i0 = 0, i1 = 0, i2 = 0;
#pragma unroll
    for (int p = 0; p < KNN; p++) {
        unsigned long long v0 = g_part[0][i0][idx];
        unsigned long long v1 = g_part[1][i1][idx];
        unsigned long long v2 = g_part[2][i2][idx];

        bool b01 = v0 <= v1; unsigned long long m01 = b01 ? v0 : v1;
        bool bf  = m01 <= v2; unsigned long long m  = bf ? m01 : v2;

        i0 += ( bf &&  b01) ? 1 : 0;
        i1 += ( bf && !b01) ? 1 : 0;
        i2 += (!bf)         ? 1 : 0;

        out[base0 + p] = (float)(int)(unsigned int)(m & 0xffffffffu);
        out[base1 + p] = ftgt;
    }
}

// ---------------------------------------------------------------------------
extern "C" void kernel_launch(void* const* d_in, const int* in_sizes, int n_in,
                              void* d_out, int out_size) {
    (void)in_sizes; (void)n_in; (void)out_size;
    const float* x = (const float*)d_in[0];
    float* out = (float*)d_out;

    sq_all<<<(BATCH * NPTS) / 256, 256>>>(x);
    dim3 grid(NPTS / TM, BATCH, NSPLIT);        // 32 x 8 x 3 = 768 CTAs
    knn_part<<<grid, TM>>>(x);
    knn_merge<<<(BATCH * NPTS) / 256, 256>>>(out);
}

// round 16
// speedup vs baseline: 1.2316x; 1.2316x over previous
#include <cuda_runtime.h>
#include <cstdint>

// Fixed problem shape
#define BATCH 8
#define CDIM  64
#define NPTS  4096
#define KNN   20
#define TM    128    // targets per block == threads per block
#define TC    32     // candidate tile size
#define CAP   18     // per-thread buffer slots (trigger cnt>2; <=16 appends/group)
#define NSPLIT 2
#define HALF_N (NPTS / NSPLIT)
#define TROW  (CDIM + 1)          // 64 channel rows + 1 csq row

// Cross-kernel scratch (device globals are legal; no allocations).
__device__ float g_csq[BATCH * NPTS];
__device__ unsigned long long g_part[NSPLIT][KNN][BATCH * NPTS];

// Packed helpers: fma.rn.f32x2 = two independent rn-rounded fp32 FMAs.
__device__ __forceinline__ void fma2(unsigned long long& acc,
                                     unsigned long long a2,
                                     unsigned long long b2) {
    asm("fma.rn.f32x2 %0, %1, %2, %0;" : "+l"(acc) : "l"(a2), "l"(b2));
}
__device__ __forceinline__ unsigned long long dup2(float a) {
    unsigned long long r;
    asm("mov.b64 %0, {%1, %1};" : "=l"(r) : "f"(a));
    return r;
}
__device__ __forceinline__ void unpack2(unsigned long long v, float& lo, float& hi) {
    asm("mov.b64 {%0, %1}, %2;" : "=f"(lo), "=f"(hi) : "l"(v));
}
// cp.async helpers (16B chunks).
__device__ __forceinline__ void cp_async16(const float* smem_dst, const float* gmem_src) {
    uint32_t s = (uint32_t)__cvta_generic_to_shared(smem_dst);
    asm volatile("cp.async.ca.shared.global [%0], [%1], 16;" :: "r"(s), "l"(gmem_src));
}
#define CP_COMMIT() asm volatile("cp.async.commit_group;" ::: "memory")
#define CP_WAIT0()  asm volatile("cp.async.wait_group 0;" ::: "memory")

// ---------------------------------------------------------------------------
// Prologue: g_csq[b][n] = sum_c x[b][c][n]^2, ascending-c sequential FMA —
// bit-identical to every passing round's csq.
// ---------------------------------------------------------------------------
__global__ void __launch_bounds__(256) sq_all(const float* __restrict__ x) {
    int idx = blockIdx.x * 256 + threadIdx.x;   // 0 .. B*N-1
    int b = idx >> 12;
    int n = idx & (NPTS - 1);
    const float* xb = x + b * CDIM * NPTS;
    float s = 0.f;
#pragma unroll
    for (int c = 0; c < CDIM; c++) {
        float v = xb[c * NPTS + n];             // coalesced
        s = fmaf(v, v, s);
    }
    g_csq[idx] = s;
}

// ---------------------------------------------------------------------------
// Kernel 1: the 789us round-14 kernel with ONE change: inner candidate group
// widened 8 -> 16 (8 independent FFMA2 accumulator chains, 4x LDS.128 per
// channel) to cover the 29-cyc LDS latency with in-loop ILP. Per-candidate
// arithmetic chains are unchanged (own accumulator, sequential ascending-c
// FMA; d2 = fma(dot, -2, sqt + csq)) -> bit-identical results.
// Top-K: threshold + deferred buffer merge on packed u64 keys
// (d2_bits<<32 | idx) == exact lax.top_k (dist asc, lower idx first).
// ---------------------------------------------------------------------------
__global__ void __launch_bounds__(TM, 4) knn_half(const float* __restrict__ x) {
    __shared__ __align__(16) float s_tile[2][TROW * TC];    // 2 x 8.125 KB
    __shared__ unsigned long long s_top[KNN][TM];           // 20 KB sorted topK
    __shared__ unsigned long long s_buf[CAP][TM];           // 18 KB buffers

    const int b    = blockIdx.y;
    const int half = blockIdx.z;
    const int tid  = threadIdx.x;
    const int tgt  = blockIdx.x * TM + tid;
    const float* xb = x + b * CDIM * NPTS;
    const float* cq = g_csq + b * NPTS;
    const int jbeg = half * HALF_N;
    const int NT   = HALF_N / TC;               // 64 tiles

    // Target features -> registers; target squared norm (ascending c).
    float tq[CDIM];
    float sqt = 0.f;
#pragma unroll
    for (int c = 0; c < CDIM; c++) {
        tq[c] = xb[c * NPTS + tgt];
        sqt = fmaf(tq[c], tq[c], sqt);
    }

#pragma unroll
    for (int k = 0; k < KNN; k++) s_top[k][tid] = ~0ull;
    unsigned long long thresh = ~0ull;
    int cnt = 0;

    // Stage one tile (64 channel rows + csq row) into buffer nb.
    auto stage = [&](int nb, int j0) {
        float* dst = s_tile[nb];
#pragma unroll
        for (int k = 0; k < 4; k++) {
            int cid = tid * 4 + k;              // 0..511 chunk id
            int c = cid >> 3, i = cid & 7;
            cp_async16(dst + c * TC + i * 4, xb + c * NPTS + j0 + i * 4);
        }
        if (tid < 8)
            cp_async16(dst + CDIM * TC + tid * 4, cq + j0 + tid * 4);
        CP_COMMIT();
    };

    stage(0, jbeg);                             // preload tile 0

    for (int t = 0; t < NT; t++) {
        const int cur = t & 1;
        const int j0  = jbeg + t * TC;
        CP_WAIT0();                             // tile t fully arrived
        __syncthreads();                        // visible to all; prev compute done
        if (t + 1 < NT) stage(cur ^ 1, j0 + TC);// overlaps compute below

        const float* sf  = s_tile[cur];
        const float* csq = sf + CDIM * TC;

        for (int jg = 0; jg < TC; jg += 16) {
            unsigned long long acc[8] = {0, 0, 0, 0, 0, 0, 0, 0};
#pragma unroll
            for (int c = 0; c < CDIM; c++) {
                const ulonglong2* rp =
                    reinterpret_cast<const ulonglong2*>(sf + c * TC + jg);
                ulonglong2 v0 = rp[0];          // cands jg..jg+3
                ulonglong2 v1 = rp[1];          // cands jg+4..jg+7
                ulonglong2 v2 = rp[2];          // cands jg+8..jg+11
                ulonglong2 v3 = rp[3];          // cands jg+12..jg+15
                unsigned long long a2 = dup2(tq[c]);
                fma2(acc[0], a2, v0.x);
                fma2(acc[1], a2, v0.y);
                fma2(acc[2], a2, v1.x);
                fma2(acc[3], a2, v1.y);
                fma2(acc[4], a2, v2.x);
                fma2(acc[5], a2, v2.y);
                fma2(acc[6], a2, v3.x);
                fma2(acc[7], a2, v3.y);
            }
            float dots[16];
#pragma unroll
            for (int q = 0; q < 8; q++)
                unpack2(acc[q], dots[2 * q], dots[2 * q + 1]);

            float csv[16];
#pragma unroll
            for (int q = 0; q < 4; q++) {
                float4 cs = *reinterpret_cast<const float4*>(csq + jg + 4 * q);
                csv[4 * q + 0] = cs.x; csv[4 * q + 1] = cs.y;
                csv[4 * q + 2] = cs.z; csv[4 * q + 3] = cs.w;
            }
#pragma unroll
            for (int u = 0; u < 16; u++) {
                int   j = j0 + jg + u;
                float ts = sqt + csv[u];
                float d  = fmaf(dots[u], -2.0f, ts);  // one final rounding
                unsigned long long key =
                    ((unsigned long long)__float_as_uint(d) << 32) |
                    (unsigned int)j;
                // Branchless append (R14-proven): unconditional store,
                // predicated count. Junk beyond cnt is never read.
                s_buf[cnt][tid] = key;
                cnt += (int)((j != tgt) & (key < thresh));
            }
            // Deferred warp-wide merge; cnt<=2 carries + <=16 appends <= CAP.
            if (__any_sync(0xffffffffu, cnt > 2)) {
                for (int i = 0; i < cnt; i++) {
                    unsigned long long kv = s_buf[i][tid];
                    if (kv < s_top[KNN - 1][tid]) {
                        int k = KNN - 1;
                        while (k > 0 && s_top[k - 1][tid] > kv) {
                            s_top[k][tid] = s_top[k - 1][tid];
                            k--;
                        }
                        s_top[k][tid] = kv;
                    }
                }
                cnt = 0;
                thresh = s_top[KNN - 1][tid];
            }
        }
        __syncthreads();                        // done reading buf[cur] before
                                                // iter t+1 overwrites it
    }

    for (int i = 0; i < cnt; i++) {             // leftovers
        unsigned long long kv = s_buf[i][tid];
        if (kv < s_top[KNN - 1][tid]) {
            int k = KNN - 1;
            while (k > 0 && s_top[k - 1][tid] > kv) {
                s_top[k][tid] = s_top[k - 1][tid];
                k--;
            }
            s_top[k][tid] = kv;
        }
    }

    // Write sorted partial top-20 (coalesced in target index).
    const int col = b * NPTS + tgt;
#pragma unroll
    for (int p = 0; p < KNN; p++)
        g_part[half][p][col] = s_top[p][tid];
}

// ---------------------------------------------------------------------------
// Kernel 2: exact 2-pointer merge of the two sorted per-half top-20 lists.
// ---------------------------------------------------------------------------
__global__ void __launch_bounds__(128) knn_merge(float* __restrict__ out) {
    __shared__ unsigned long long sa[KNN][128];
    __shared__ unsigned long long sb[KNN][128];
    const int t   = threadIdx.x;
    const int idx = blockIdx.x * 128 + t;       // 0 .. B*N-1
#pragma unroll
    for (int p = 0; p < KNN; p++) {
        sa[p][t] = g_part[0][p][idx];           // coalesced
        sb[p][t] = g_part[1][p][idx];
    }
    const int b = idx >> 12;                    // NPTS = 4096
    const int n = idx & (NPTS - 1);
    const int base0 = ((0 * BATCH + b) * NPTS + n) * KNN;
    const int base1 = ((1 * BATCH + b) * NPTS + n) * KNN;
    const float ftgt = (float)n;

    int ia = 0, ib = 0;
#pragma unroll
    for (int p = 0; p < KNN; p++) {
        unsigned long long va = sa[ia][t];
        unsigned long long vb = sb[ib][t];
        bool ta = va < vb;                      // u64 order == exact key order
        unsigned long long v = ta ? va : vb;
        ia += ta ? 1 : 0;
        ib += ta ? 0 : 1;
        out[base0 + p] = (float)(int)(unsigned int)(v & 0xffffffffu);
        out[base1 + p] = ftgt;
    }
}

// ---------------------------------------------------------------------------
extern "C" void kernel_launch(void* const* d_in, const int* in_sizes, int n_in,
                              void* d_out, int out_size) {
    (void)in_sizes; (void)n_in; (void)out_size;
    const float* x = (const float*)d_in[0];
    float* out = (float*)d_out;

    sq_all<<<(BATCH * NPTS) / 256, 256>>>(x);
    dim3 grid(NPTS / TM, BATCH, NSPLIT);        // 32 x 8 x 2 = 512 CTAs
    knn_half<<<grid, TM>>>(x);
    knn_merge<<<(BATCH * NPTS) / 128, 128>>>(out);
}